// round 4
// baseline (speedup 1.0000x reference)
#include <cuda_runtime.h>
#include <cstdint>
#include <math.h>

// Problem constants
constexpr int B_ROWS = 8192;   // batch
constexpr int FDIM   = 4096;   // features
constexpr int NINT   = 511;    // internal nodes
constexpr int NPAD   = 512;    // padded internal/leaf dim
constexpr int NLEAF  = 512;
constexpr int KOUT   = 1000;

// Scratch (device globals; allocation is forbidden)
__device__ float g_ps[(size_t)B_ROWS * NPAD];     // sigmoid(logits), padded to 512 cols
__device__ float g_lp[(size_t)B_ROWS * NLEAF];    // leaf probabilities
__device__ float g_dists[(size_t)NLEAF * KOUT];   // softmax(leaf_params)

// ---------------------------------------------------------------------------
// tf32 helpers
// ---------------------------------------------------------------------------
__device__ __forceinline__ uint32_t f2tf(float f) {
    uint32_t u;
    asm("cvt.rna.tf32.f32 %0, %1;" : "=r"(u) : "f"(f));
    return u;
}

__device__ __forceinline__ void mma8(float* c, const uint32_t* a, uint32_t b0, uint32_t b1) {
    asm volatile(
        "mma.sync.aligned.m16n8k8.row.col.f32.tf32.tf32.f32 "
        "{%0,%1,%2,%3}, {%4,%5,%6,%7}, {%8,%9}, {%0,%1,%2,%3};\n"
        : "+f"(c[0]), "+f"(c[1]), "+f"(c[2]), "+f"(c[3])
        : "r"(a[0]), "r"(a[1]), "r"(a[2]), "r"(a[3]), "r"(b0), "r"(b1));
}

// ---------------------------------------------------------------------------
// GEMM1: ps = sigmoid(xs @ W^T + b)   [8192,4096] x [511,4096]^T -> [8192,512]
// BM=128 BN=128 BK=16, 8 warps (4m x 2n), warp tile 32x64, tf32 mma.
// Both A and B are K-major rows -> identical smem layout [128][20].
// ---------------------------------------------------------------------------
constexpr int AS1 = 20;   // padded stride (conflict-free for fragment LDS pattern)

__global__ __launch_bounds__(256, 2)
void gemm1_kernel(const float* __restrict__ xs, const float* __restrict__ W,
                  const float* __restrict__ bias)
{
    __shared__ float As[2][128 * AS1];
    __shared__ float Bs[2][128 * AS1];

    const int tn = blockIdx.x;        // 0..3  (N tiles)
    const int tm = blockIdx.y;        // 0..63 (M tiles)
    const int tid  = threadIdx.x;
    const int warp = tid >> 5, lane = tid & 31;
    const int wm = warp & 3;          // m sub-tile (32 rows each)
    const int wn = warp >> 2;         // n sub-tile (64 cols each)
    const int g  = lane >> 2, tg = lane & 3;

    float c[2][8][4];
    #pragma unroll
    for (int i = 0; i < 2; i++)
        #pragma unroll
        for (int j = 0; j < 8; j++)
            #pragma unroll
            for (int k = 0; k < 4; k++) c[i][j][k] = 0.f;

    // Global load mapping: each thread loads 8 contiguous floats of one row.
    const int lr = tid >> 1;          // 0..127 (tile row)
    const int lc = (tid & 1) * 8;     // 0 or 8
    const float* Ag = xs + (size_t)(tm * 128 + lr) * FDIM + lc;
    const int brow = tn * 128 + lr;
    const float* Bg = W + (size_t)brow * FDIM + lc;
    const bool bvalid = (brow < NINT);

    float4 ra0, ra1, rb0, rb1;
    auto ldg_tile = [&](int kt) {
        const float* a = Ag + kt * 16;
        ra0 = *(const float4*)a;
        ra1 = *(const float4*)(a + 4);
        if (bvalid) {
            const float* bb = Bg + kt * 16;
            rb0 = *(const float4*)bb;
            rb1 = *(const float4*)(bb + 4);
        } else {
            rb0 = make_float4(0.f, 0.f, 0.f, 0.f);
            rb1 = rb0;
        }
    };
    auto sts_tile = [&](int buf) {
        *(float4*)&As[buf][lr * AS1 + lc]     = ra0;
        *(float4*)&As[buf][lr * AS1 + lc + 4] = ra1;
        *(float4*)&Bs[buf][lr * AS1 + lc]     = rb0;
        *(float4*)&Bs[buf][lr * AS1 + lc + 4] = rb1;
    };
    auto compute = [&](int buf) {
        #pragma unroll
        for (int ks = 0; ks < 2; ks++) {
            const int kb = ks * 8;
            uint32_t af[2][4];
            #pragma unroll
            for (int mt = 0; mt < 2; mt++) {
                const int row = wm * 32 + mt * 16 + g;
                af[mt][0] = f2tf(As[buf][row       * AS1 + kb + tg]);
                af[mt][1] = f2tf(As[buf][(row + 8) * AS1 + kb + tg]);
                af[mt][2] = f2tf(As[buf][row       * AS1 + kb + tg + 4]);
                af[mt][3] = f2tf(As[buf][(row + 8) * AS1 + kb + tg + 4]);
            }
            #pragma unroll
            for (int nt = 0; nt < 8; nt++) {
                const int col = wn * 64 + nt * 8 + g;
                uint32_t b0 = f2tf(Bs[buf][col * AS1 + kb + tg]);
                uint32_t b1 = f2tf(Bs[buf][col * AS1 + kb + tg + 4]);
                mma8(c[0][nt], af[0], b0, b1);
                mma8(c[1][nt], af[1], b0, b1);
            }
        }
    };

    constexpr int KT = FDIM / 16;   // 256
    ldg_tile(0);
    sts_tile(0);
    __syncthreads();
    int cur = 0;
    for (int kt = 0; kt < KT; kt++) {
        if (kt + 1 < KT) ldg_tile(kt + 1);
        compute(cur);
        if (kt + 1 < KT) {
            sts_tile(cur ^ 1);
            __syncthreads();
            cur ^= 1;
        }
    }

    // Epilogue: bias + sigmoid, write ps (float2 stores, cols are even-aligned)
    #pragma unroll
    for (int mt = 0; mt < 2; mt++) {
        #pragma unroll
        for (int nt = 0; nt < 8; nt++) {
            const int col = tn * 128 + wn * 64 + nt * 8 + 2 * tg;
            const float bb0 = (col     < NINT) ? bias[col]     : 0.f;
            const float bb1 = (col + 1 < NINT) ? bias[col + 1] : 0.f;
            const int row0 = tm * 128 + wm * 32 + mt * 16 + g;
            float v0 = c[mt][nt][0] + bb0;
            float v1 = c[mt][nt][1] + bb1;
            float v2 = c[mt][nt][2] + bb0;
            float v3 = c[mt][nt][3] + bb1;
            float2 p0 = make_float2(1.f / (1.f + __expf(-v0)), 1.f / (1.f + __expf(-v1)));
            float2 p1 = make_float2(1.f / (1.f + __expf(-v2)), 1.f / (1.f + __expf(-v3)));
            *(float2*)&g_ps[(size_t)row0      * NPAD + col] = p0;
            *(float2*)&g_ps[(size_t)(row0 + 8) * NPAD + col] = p1;
        }
    }
}

// ---------------------------------------------------------------------------
// Leaf probabilities: one block per row, 512 threads (one per leaf)
// ---------------------------------------------------------------------------
__global__ void leaf_kernel()
{
    __shared__ float sp[NINT];
    const int row = blockIdx.x;
    const int j = threadIdx.x;
    if (j < NINT) sp[j] = g_ps[(size_t)row * NPAD + j];
    __syncthreads();
    float prod = 1.f;
    int node = 0;
    #pragma unroll
    for (int t = 0; t < 9; t++) {
        const int bit = (j >> (8 - t)) & 1;
        const float p = sp[node];
        prod *= bit ? p : (1.f - p);
        node = 2 * node + 1 + bit;
    }
    g_lp[(size_t)row * NLEAF + j] = prod;
}

// ---------------------------------------------------------------------------
// Softmax over leaf_params rows: one block per leaf (512 blocks, 256 threads)
// ---------------------------------------------------------------------------
__global__ void softmax_kernel(const float* __restrict__ lp)
{
    const int row = blockIdx.x;
    const int tid = threadIdx.x;
    const float* src = lp + (size_t)row * KOUT;
    __shared__ float red[8];

    float m = -1e30f;
    for (int i = tid; i < KOUT; i += 256) m = fmaxf(m, src[i]);
    #pragma unroll
    for (int o = 16; o > 0; o >>= 1) m = fmaxf(m, __shfl_xor_sync(0xffffffffu, m, o));
    if ((tid & 31) == 0) red[tid >> 5] = m;
    __syncthreads();
    if (tid < 32) {
        float v = (tid < 8) ? red[tid] : -1e30f;
        #pragma unroll
        for (int o = 4; o > 0; o >>= 1) v = fmaxf(v, __shfl_xor_sync(0xffffffffu, v, o));
        if (tid == 0) red[0] = v;
    }
    __syncthreads();
    m = red[0];
    __syncthreads();

    float s = 0.f;
    for (int i = tid; i < KOUT; i += 256) s += __expf(src[i] - m);
    #pragma unroll
    for (int o = 16; o > 0; o >>= 1) s += __shfl_xor_sync(0xffffffffu, s, o);
    if ((tid & 31) == 0) red[tid >> 5] = s;
    __syncthreads();
    if (tid < 32) {
        float v = (tid < 8) ? red[tid] : 0.f;
        #pragma unroll
        for (int o = 4; o > 0; o >>= 1) v += __shfl_xor_sync(0xffffffffu, v, o);
        if (tid == 0) red[0] = v;
    }
    __syncthreads();
    const float inv = 1.f / red[0];
    for (int i = tid; i < KOUT; i += 256)
        g_dists[(size_t)row * KOUT + i] = __expf(src[i] - m) * inv;
}

// ---------------------------------------------------------------------------
// GEMM2: out = leaf_prob[8192,512] @ dists[512,1000]
// BM=128 BN=128 BK=16, K=512 (32 iters), N padded to 1024 with guards.
// A layout [128][20] (row-major rows), B layout [16][136] (k-major rows).
// ---------------------------------------------------------------------------
constexpr int AS2 = 20;
constexpr int BS2 = 136;

__global__ __launch_bounds__(256, 2)
void gemm2_kernel(float* __restrict__ out)
{
    __shared__ float As[2][128 * AS2];
    __shared__ float Bs[2][16 * BS2];

    const int tn = blockIdx.x;        // 0..7
    const int tm = blockIdx.y;        // 0..63
    const int tid  = threadIdx.x;
    const int warp = tid >> 5, lane = tid & 31;
    const int wm = warp & 3, wn = warp >> 2;
    const int g  = lane >> 2, tg = lane & 3;

    float c[2][8][4];
    #pragma unroll
    for (int i = 0; i < 2; i++)
        #pragma unroll
        for (int j = 0; j < 8; j++)
            #pragma unroll
            for (int k = 0; k < 4; k++) c[i][j][k] = 0.f;

    // A load mapping (same as gemm1, row stride 512)
    const int lr = tid >> 1;
    const int lc = (tid & 1) * 8;
    const float* Ag = g_lp + (size_t)(tm * 128 + lr) * NLEAF + lc;

    // B load mapping: k = tid>>4 (0..15), 8 contiguous n per thread
    const int bk = tid >> 4;
    const int bn = (tid & 15) * 8;
    const int ncol = tn * 128 + bn;               // global N col base for this thread
    const bool nvalid = (ncol < KOUT);            // KOUT divisible by 8 -> all-or-nothing

    float4 ra0, ra1, rb0, rb1;
    auto ldg_tile = [&](int kt) {
        const float* a = Ag + kt * 16;
        ra0 = *(const float4*)a;
        ra1 = *(const float4*)(a + 4);
        if (nvalid) {
            const float* bb = g_dists + (size_t)(kt * 16 + bk) * KOUT + ncol;
            rb0 = *(const float4*)bb;
            rb1 = *(const float4*)(bb + 4);
        } else {
            rb0 = make_float4(0.f, 0.f, 0.f, 0.f);
            rb1 = rb0;
        }
    };
    auto sts_tile = [&](int buf) {
        *(float4*)&As[buf][lr * AS2 + lc]     = ra0;
        *(float4*)&As[buf][lr * AS2 + lc + 4] = ra1;
        *(float4*)&Bs[buf][bk * BS2 + bn]     = rb0;
        *(float4*)&Bs[buf][bk * BS2 + bn + 4] = rb1;
    };
    auto compute = [&](int buf) {
        #pragma unroll
        for (int ks = 0; ks < 2; ks++) {
            const int kb = ks * 8;
            uint32_t af[2][4];
            #pragma unroll
            for (int mt = 0; mt < 2; mt++) {
                const int row = wm * 32 + mt * 16 + g;
                af[mt][0] = f2tf(As[buf][row       * AS2 + kb + tg]);
                af[mt][1] = f2tf(As[buf][(row + 8) * AS2 + kb + tg]);
                af[mt][2] = f2tf(As[buf][row       * AS2 + kb + tg + 4]);
                af[mt][3] = f2tf(As[buf][(row + 8) * AS2 + kb + tg + 4]);
            }
            #pragma unroll
            for (int nt = 0; nt < 8; nt++) {
                const int col = wn * 64 + nt * 8 + g;
                uint32_t b0 = f2tf(Bs[buf][(kb + tg)     * BS2 + col]);
                uint32_t b1 = f2tf(Bs[buf][(kb + tg + 4) * BS2 + col]);
                mma8(c[0][nt], af[0], b0, b1);
                mma8(c[1][nt], af[1], b0, b1);
            }
        }
    };

    constexpr int KT = NLEAF / 16;  // 32
    ldg_tile(0);
    sts_tile(0);
    __syncthreads();
    int cur = 0;
    for (int kt = 0; kt < KT; kt++) {
        if (kt + 1 < KT) ldg_tile(kt + 1);
        compute(cur);
        if (kt + 1 < KT) {
            sts_tile(cur ^ 1);
            __syncthreads();
            cur ^= 1;
        }
    }

    #pragma unroll
    for (int mt = 0; mt < 2; mt++) {
        #pragma unroll
        for (int nt = 0; nt < 8; nt++) {
            const int col = tn * 128 + wn * 64 + nt * 8 + 2 * tg;
            if (col < KOUT) {   // col even, KOUT even -> pair always in-bounds
                const int row0 = tm * 128 + wm * 32 + mt * 16 + g;
                *(float2*)&out[(size_t)row0      * KOUT + col] =
                    make_float2(c[mt][nt][0], c[mt][nt][1]);
                *(float2*)&out[(size_t)(row0 + 8) * KOUT + col] =
                    make_float2(c[mt][nt][2], c[mt][nt][3]);
            }
        }
    }
}

// ---------------------------------------------------------------------------
// Launch
// ---------------------------------------------------------------------------
extern "C" void kernel_launch(void* const* d_in, const int* in_sizes, int n_in,
                              void* d_out, int out_size)
{
    const float* xs          = (const float*)d_in[0];   // [8192, 4096]
    const float* W           = (const float*)d_in[1];   // [511, 4096]
    const float* b           = (const float*)d_in[2];   // [511]
    const float* leaf_params = (const float*)d_in[3];   // [512, 1000]
    float* out = (float*)d_out;                         // [8192, 1000]

    softmax_kernel<<<NLEAF, 256>>>(leaf_params);
    gemm1_kernel<<<dim3(4, 64), 256>>>(xs, W, b);
    leaf_kernel<<<B_ROWS, 512>>>();
    gemm2_kernel<<<dim3(8, 64), 256>>>(out);
}

// round 5
// speedup vs baseline: 1.5991x; 1.5991x over previous
#include <cuda_runtime.h>
#include <cuda_fp16.h>
#include <cstdint>
#include <math.h>

// Problem constants
constexpr int B_ROWS = 8192;   // batch
constexpr int FDIM   = 4096;   // features
constexpr int NINT   = 511;    // internal nodes
constexpr int NPAD   = 512;    // padded internal/leaf dim
constexpr int NLEAF  = 512;
constexpr int KOUT   = 1000;

// Scratch (device globals; allocation is forbidden)
__device__ float  g_ps[(size_t)B_ROWS * NPAD];     // sigmoid(logits), fp32
__device__ __half g_lp[(size_t)B_ROWS * NLEAF];    // leaf probabilities, fp16
__device__ __half g_dists[(size_t)NLEAF * KOUT];   // softmax(leaf_params), fp16

// ---------------------------------------------------------------------------
// helpers
// ---------------------------------------------------------------------------
__device__ __forceinline__ uint32_t smem_u32(const void* p) {
    return (uint32_t)__cvta_generic_to_shared(p);
}

__device__ __forceinline__ void ldsm4(uint32_t* r, uint32_t addr) {
    asm volatile("ldmatrix.sync.aligned.m8n8.x4.shared.b16 {%0,%1,%2,%3}, [%4];"
        : "=r"(r[0]), "=r"(r[1]), "=r"(r[2]), "=r"(r[3]) : "r"(addr));
}
__device__ __forceinline__ void ldsm4t(uint32_t* r, uint32_t addr) {
    asm volatile("ldmatrix.sync.aligned.m8n8.x4.trans.shared.b16 {%0,%1,%2,%3}, [%4];"
        : "=r"(r[0]), "=r"(r[1]), "=r"(r[2]), "=r"(r[3]) : "r"(addr));
}

__device__ __forceinline__ void mma16(float* c, const uint32_t* a, const uint32_t* b) {
    asm volatile(
        "mma.sync.aligned.m16n8k16.row.col.f32.f16.f16.f32 "
        "{%0,%1,%2,%3}, {%4,%5,%6,%7}, {%8,%9}, {%0,%1,%2,%3};\n"
        : "+f"(c[0]), "+f"(c[1]), "+f"(c[2]), "+f"(c[3])
        : "r"(a[0]), "r"(a[1]), "r"(a[2]), "r"(a[3]), "r"(b[0]), "r"(b[1]));
}

// pack 8 fp32 -> 8 fp16 in a uint4
__device__ __forceinline__ uint4 pack8(float4 a, float4 b) {
    uint4 r;
    __half2 h;
    h = __floats2half2_rn(a.x, a.y); r.x = *(uint32_t*)&h;
    h = __floats2half2_rn(a.z, a.w); r.y = *(uint32_t*)&h;
    h = __floats2half2_rn(b.x, b.y); r.z = *(uint32_t*)&h;
    h = __floats2half2_rn(b.z, b.w); r.w = *(uint32_t*)&h;
    return r;
}

// XOR-swizzled byte offsets, 16B chunk granularity.
// Rows of 64 bytes (32 halves), chunk in 0..3:
__device__ __forceinline__ uint32_t sw64(int row, int chunk) {
    return row * 64 + ((chunk ^ ((row >> 1) & 3)) << 4);
}
// Rows of 256 bytes (128 halves), chunk in 0..15:
__device__ __forceinline__ uint32_t sw256(int row, int chunk) {
    int swc = (chunk & 8) | ((chunk & 7) ^ (row & 7));
    return row * 256 + (swc << 4);
}

// ---------------------------------------------------------------------------
// GEMM1: ps = sigmoid(xs @ W^T + b)   [8192,4096] x [511,4096]^T -> [8192,512]
// BM=BN=128, BK=32, fp16 m16n8k16, ldmatrix fragments, swizzled smem.
// ---------------------------------------------------------------------------
__global__ __launch_bounds__(256, 2)
void gemm1_kernel(const float* __restrict__ xs, const float* __restrict__ W,
                  const float* __restrict__ bias)
{
    __shared__ __align__(16) char As[2][128 * 64];
    __shared__ __align__(16) char Bs[2][128 * 64];

    const int tn = blockIdx.x;        // 0..3
    const int tm = blockIdx.y;        // 0..63
    const int tid  = threadIdx.x;
    const int warp = tid >> 5, lane = tid & 31;
    const int wm = warp & 3;          // 32-row sub-tile
    const int wn = warp >> 2;         // 64-col sub-tile
    const int g  = lane >> 2, tg = lane & 3;

    float c[2][8][4];
    #pragma unroll
    for (int i = 0; i < 2; i++)
        #pragma unroll
        for (int j = 0; j < 8; j++)
            #pragma unroll
            for (int k = 0; k < 4; k++) c[i][j][k] = 0.f;

    // Global load mapping: each thread handles 16 floats of one row per tile.
    const int lr = tid >> 1;          // 0..127
    const int lc = tid & 1;           // col base = lc*16
    const float* Ag = xs + (size_t)(tm * 128 + lr) * FDIM + lc * 16;
    const int brow = tn * 128 + lr;
    const float* Bg = W + (size_t)brow * FDIM + lc * 16;
    const bool bvalid = (brow < NINT);

    uint4 sa0, sa1, sb0, sb1;
    auto ldg_tile = [&](int kt) {
        const float4* a = (const float4*)(Ag + kt * 32);
        float4 f0 = a[0], f1 = a[1], f2 = a[2], f3 = a[3];
        sa0 = pack8(f0, f1); sa1 = pack8(f2, f3);
        if (bvalid) {
            const float4* bb = (const float4*)(Bg + kt * 32);
            float4 h0 = bb[0], h1 = bb[1], h2 = bb[2], h3 = bb[3];
            sb0 = pack8(h0, h1); sb1 = pack8(h2, h3);
        } else {
            sb0 = make_uint4(0, 0, 0, 0); sb1 = sb0;
        }
    };
    auto sts_tile = [&](int buf) {
        const int c0 = lc * 2;
        *(uint4*)&As[buf][sw64(lr, c0)]     = sa0;
        *(uint4*)&As[buf][sw64(lr, c0 + 1)] = sa1;
        *(uint4*)&Bs[buf][sw64(lr, c0)]     = sb0;
        *(uint4*)&Bs[buf][sw64(lr, c0 + 1)] = sb1;
    };
    auto compute = [&](int buf) {
        #pragma unroll
        for (int ks = 0; ks < 2; ks++) {
            const int kc = ks * 2 + (lane >> 4);
            uint32_t a[2][4];
            #pragma unroll
            for (int mt = 0; mt < 2; mt++) {
                const int r = wm * 32 + mt * 16 + (lane & 15);
                ldsm4(a[mt], smem_u32(&As[buf][sw64(r, kc)]));
            }
            #pragma unroll
            for (int nt = 0; nt < 4; nt++) {
                uint32_t b[4];
                const int nr = wn * 64 + nt * 16 + (lane & 15);
                ldsm4(b, smem_u32(&Bs[buf][sw64(nr, kc)]));
                // non-trans x4: b[0]=n0-7/k0-7, b[1]=n8-15/k0-7, b[2]=n0-7/k8-15, b[3]=n8-15/k8-15
                uint32_t blo[2] = { b[0], b[2] };
                uint32_t bhi[2] = { b[1], b[3] };
                mma16(c[0][nt * 2],     a[0], blo);
                mma16(c[1][nt * 2],     a[1], blo);
                mma16(c[0][nt * 2 + 1], a[0], bhi);
                mma16(c[1][nt * 2 + 1], a[1], bhi);
            }
        }
    };

    constexpr int KT = FDIM / 32;   // 128
    ldg_tile(0);
    sts_tile(0);
    __syncthreads();
    int cur = 0;
    for (int kt = 0; kt < KT; kt++) {
        if (kt + 1 < KT) ldg_tile(kt + 1);
        compute(cur);
        if (kt + 1 < KT) {
            sts_tile(cur ^ 1);
            __syncthreads();
            cur ^= 1;
        }
    }

    // Epilogue: bias + sigmoid -> g_ps (fp32)
    #pragma unroll
    for (int mt = 0; mt < 2; mt++) {
        #pragma unroll
        for (int j = 0; j < 8; j++) {
            const int col = tn * 128 + wn * 64 + j * 8 + 2 * tg;
            const float bb0 = (col     < NINT) ? bias[col]     : 0.f;
            const float bb1 = (col + 1 < NINT) ? bias[col + 1] : 0.f;
            const int row0 = tm * 128 + wm * 32 + mt * 16 + g;
            float v0 = c[mt][j][0] + bb0;
            float v1 = c[mt][j][1] + bb1;
            float v2 = c[mt][j][2] + bb0;
            float v3 = c[mt][j][3] + bb1;
            float2 p0 = make_float2(1.f / (1.f + __expf(-v0)), 1.f / (1.f + __expf(-v1)));
            float2 p1 = make_float2(1.f / (1.f + __expf(-v2)), 1.f / (1.f + __expf(-v3)));
            *(float2*)&g_ps[(size_t)row0       * NPAD + col] = p0;
            *(float2*)&g_ps[(size_t)(row0 + 8) * NPAD + col] = p1;
        }
    }
}

// ---------------------------------------------------------------------------
// Leaf probabilities: one block per row, 512 threads (one per leaf), fp16 out
// ---------------------------------------------------------------------------
__global__ void leaf_kernel()
{
    __shared__ float sp[NINT];
    const int row = blockIdx.x;
    const int j = threadIdx.x;
    if (j < NINT) sp[j] = g_ps[(size_t)row * NPAD + j];
    __syncthreads();
    float prod = 1.f;
    int node = 0;
    #pragma unroll
    for (int t = 0; t < 9; t++) {
        const int bit = (j >> (8 - t)) & 1;
        const float p = sp[node];
        prod *= bit ? p : (1.f - p);
        node = 2 * node + 1 + bit;
    }
    g_lp[(size_t)row * NLEAF + j] = __float2half_rn(prod);
}

// ---------------------------------------------------------------------------
// Softmax over leaf_params rows -> g_dists (fp16)
// ---------------------------------------------------------------------------
__global__ void softmax_kernel(const float* __restrict__ lp)
{
    const int row = blockIdx.x;
    const int tid = threadIdx.x;
    const float* src = lp + (size_t)row * KOUT;
    __shared__ float red[8];

    float m = -1e30f;
    for (int i = tid; i < KOUT; i += 256) m = fmaxf(m, src[i]);
    #pragma unroll
    for (int o = 16; o > 0; o >>= 1) m = fmaxf(m, __shfl_xor_sync(0xffffffffu, m, o));
    if ((tid & 31) == 0) red[tid >> 5] = m;
    __syncthreads();
    if (tid < 32) {
        float v = (tid < 8) ? red[tid] : -1e30f;
        #pragma unroll
        for (int o = 4; o > 0; o >>= 1) v = fmaxf(v, __shfl_xor_sync(0xffffffffu, v, o));
        if (tid == 0) red[0] = v;
    }
    __syncthreads();
    m = red[0];
    __syncthreads();

    float s = 0.f;
    for (int i = tid; i < KOUT; i += 256) s += __expf(src[i] - m);
    #pragma unroll
    for (int o = 16; o > 0; o >>= 1) s += __shfl_xor_sync(0xffffffffu, s, o);
    if ((tid & 31) == 0) red[tid >> 5] = s;
    __syncthreads();
    if (tid < 32) {
        float v = (tid < 8) ? red[tid] : 0.f;
        #pragma unroll
        for (int o = 4; o > 0; o >>= 1) v += __shfl_xor_sync(0xffffffffu, v, o);
        if (tid == 0) red[0] = v;
    }
    __syncthreads();
    const float inv = 1.f / red[0];
    for (int i = tid; i < KOUT; i += 256)
        g_dists[(size_t)row * KOUT + i] = __float2half_rn(__expf(src[i] - m) * inv);
}

// ---------------------------------------------------------------------------
// GEMM2: out = leaf_prob[8192,512] @ dists[512,1000]   (fp16 in, fp32 out)
// BM=BN=128, BK=32, KT=16. B fragments via ldmatrix.trans from [32][128] tile.
// ---------------------------------------------------------------------------
__global__ __launch_bounds__(256, 2)
void gemm2_kernel(float* __restrict__ out)
{
    __shared__ __align__(16) char As[2][128 * 64];
    __shared__ __align__(16) char Bs[2][32 * 256];

    const int tn = blockIdx.x;        // 0..7
    const int tm = blockIdx.y;        // 0..63
    const int tid  = threadIdx.x;
    const int warp = tid >> 5, lane = tid & 31;
    const int wm = warp & 3, wn = warp >> 2;
    const int g  = lane >> 2, tg = lane & 3;

    float c[2][8][4];
    #pragma unroll
    for (int i = 0; i < 2; i++)
        #pragma unroll
        for (int j = 0; j < 8; j++)
            #pragma unroll
            for (int k = 0; k < 4; k++) c[i][j][k] = 0.f;

    // A: 16 halves per thread per tile
    const int lr = tid >> 1;
    const int lc = tid & 1;
    const __half* Ag = g_lp + (size_t)(tm * 128 + lr) * NLEAF + lc * 16;

    // B: thread handles rows bk, bk+16; one 8-half chunk each
    const int bk = tid >> 4;          // 0..15
    const int bc = tid & 15;          // chunk (8 halves)
    const int ncol = tn * 128 + bc * 8;
    const bool nvalid = (ncol < KOUT);   // KOUT % 8 == 0 -> all-or-nothing

    uint4 sa0, sa1, sb0, sb1;
    auto ldg_tile = [&](int kt) {
        const uint4* a = (const uint4*)(Ag + kt * 32);
        sa0 = a[0]; sa1 = a[1];
        if (nvalid) {
            sb0 = *(const uint4*)(g_dists + (size_t)(kt * 32 + bk)      * KOUT + ncol);
            sb1 = *(const uint4*)(g_dists + (size_t)(kt * 32 + bk + 16) * KOUT + ncol);
        } else {
            sb0 = make_uint4(0, 0, 0, 0); sb1 = sb0;
        }
    };
    auto sts_tile = [&](int buf) {
        const int c0 = lc * 2;
        *(uint4*)&As[buf][sw64(lr, c0)]      = sa0;
        *(uint4*)&As[buf][sw64(lr, c0 + 1)]  = sa1;
        *(uint4*)&Bs[buf][sw256(bk, bc)]      = sb0;
        *(uint4*)&Bs[buf][sw256(bk + 16, bc)] = sb1;
    };
    auto compute = [&](int buf) {
        #pragma unroll
        for (int ks = 0; ks < 2; ks++) {
            const int kc = ks * 2 + (lane >> 4);
            uint32_t a[2][4];
            #pragma unroll
            for (int mt = 0; mt < 2; mt++) {
                const int r = wm * 32 + mt * 16 + (lane & 15);
                ldsm4(a[mt], smem_u32(&As[buf][sw64(r, kc)]));
            }
            #pragma unroll
            for (int nt = 0; nt < 4; nt++) {
                uint32_t b[4];
                const int krow = ks * 16 + (lane & 15);
                const int ch = wn * 8 + nt * 2 + (lane >> 4);
                ldsm4t(b, smem_u32(&Bs[buf][sw256(krow, ch)]));
                // trans x4: b[0]=k0-7/n0-7, b[1]=k8-15/n0-7, b[2]=k0-7/n8-15, b[3]=k8-15/n8-15
                mma16(c[0][nt * 2],     a[0], b);
                mma16(c[1][nt * 2],     a[1], b);
                mma16(c[0][nt * 2 + 1], a[0], b + 2);
                mma16(c[1][nt * 2 + 1], a[1], b + 2);
            }
        }
    };

    constexpr int KT = NLEAF / 32;  // 16
    ldg_tile(0);
    sts_tile(0);
    __syncthreads();
    int cur = 0;
    for (int kt = 0; kt < KT; kt++) {
        if (kt + 1 < KT) ldg_tile(kt + 1);
        compute(cur);
        if (kt + 1 < KT) {
            sts_tile(cur ^ 1);
            __syncthreads();
            cur ^= 1;
        }
    }

    #pragma unroll
    for (int mt = 0; mt < 2; mt++) {
        #pragma unroll
        for (int j = 0; j < 8; j++) {
            const int col = tn * 128 + wn * 64 + j * 8 + 2 * tg;
            if (col < KOUT) {   // col even, KOUT even -> pair always in-bounds
                const int row0 = tm * 128 + wm * 32 + mt * 16 + g;
                *(float2*)&out[(size_t)row0       * KOUT + col] =
                    make_float2(c[mt][j][0], c[mt][j][1]);
                *(float2*)&out[(size_t)(row0 + 8) * KOUT + col] =
                    make_float2(c[mt][j][2], c[mt][j][3]);
            }
        }
    }
}

// ---------------------------------------------------------------------------
// Launch
// ---------------------------------------------------------------------------
extern "C" void kernel_launch(void* const* d_in, const int* in_sizes, int n_in,
                              void* d_out, int out_size)
{
    const float* xs          = (const float*)d_in[0];   // [8192, 4096]
    const float* W           = (const float*)d_in[1];   // [511, 4096]
    const float* b           = (const float*)d_in[2];   // [511]
    const float* leaf_params = (const float*)d_in[3];   // [512, 1000]
    float* out = (float*)d_out;                         // [8192, 1000]

    softmax_kernel<<<NLEAF, 256>>>(leaf_params);
    gemm1_kernel<<<dim3(4, 64), 256>>>(xs, W, b);
    leaf_kernel<<<B_ROWS, 512>>>();
    gemm2_kernel<<<dim3(8, 64), 256>>>(out);
}